// round 2
// baseline (speedup 1.0000x reference)
#include <cuda_runtime.h>
#include <math.h>

// ---------------- constants ----------------
#define BB   4
#define CC   64
#define HH   256
#define WW   256
#define NN   65536      // HH*WW
#define HEADS 8
#define CHD  8
#define HIDD 170
#define HID2 340
#define C3   192
#define C2   128
#define BN   262144     // BB*NN

// ---------------- scratch (static device memory; allocation-free) ----------------
__device__ float d_y   [BB*CC*NN];     // LN1 out -> comb -> LN2 out (reused)
__device__ float d_xT  [BB*CC*NN];     // input transposed to (B,C,N)
__device__ float d_xi1 [BB*CC*NN];     // after attention residual
__device__ float d_g1  [BB*CC*NN];     // gelu(x1)
__device__ float d_big [BB*HID2*NN];   // qkv_pre (192ch) then FFN hidden (340ch)
__device__ float d_qkv [BB*C3*NN];     // depthwise qkv; q,k normalized in-place
__device__ float d_u   [BB*C2*NN];     // dw1 out (128ch)
__device__ float d_g2  [BB*HIDD*NN];   // gated FFN hidden (170ch)
__device__ float d_ref [BB*HEADS*NN];  // sigmoid(refine)
__device__ float d_meanpart[BB*CC*64];
__device__ float d_xsca[BB*CC];
__device__ float d_attnpart[32*64*80];
__device__ float d_attnm[32*80];

__device__ __forceinline__ float gelu_exact(float x) {
    return 0.5f * x * (1.f + erff(x * 0.70710678118654752f));
}

// ---------------- BiasFree LayerNorm ----------------
// LAYOUT 0: in is (B,N,C) channel-last (the raw input x); also writes xT (B,C,N).
// LAYOUT 1: in is (B,C,N).
template<int LAYOUT>
__global__ void ln_kernel(const float* __restrict__ in, const float* __restrict__ w,
                          float* __restrict__ out, float* __restrict__ xT)
{
    int gid = blockIdx.x * 256 + threadIdx.x;   // 0..BN-1
    int b = gid >> 16;
    int n = gid & (NN - 1);
    float v[CC];
    if (LAYOUT == 0) {
        const float4* p = reinterpret_cast<const float4*>(in + (size_t)gid * CC);
        #pragma unroll
        for (int i = 0; i < 16; i++) {
            float4 t = p[i];
            v[4*i] = t.x; v[4*i+1] = t.y; v[4*i+2] = t.z; v[4*i+3] = t.w;
        }
    } else {
        #pragma unroll
        for (int c = 0; c < CC; c++) v[c] = in[((size_t)b*CC + c)*NN + n];
    }
    float s = 0.f, s2 = 0.f;
    #pragma unroll
    for (int c = 0; c < CC; c++) { s += v[c]; s2 += v[c]*v[c]; }
    float mean = s * (1.f / CC);
    float var  = s2 * (1.f / CC) - mean * mean;
    float inv  = rsqrtf(var + 1e-5f);
    #pragma unroll
    for (int c = 0; c < CC; c++) {
        size_t o = ((size_t)b*CC + c)*NN + n;
        out[o] = v[c] * inv * __ldg(&w[c]);
        if (LAYOUT == 0) xT[o] = v[c];
    }
}

// ---------------- channel mean of LN1 output (stage 1) ----------------
__global__ void mean1_kernel(const float* __restrict__ y, float* __restrict__ part)
{
    int chunk = blockIdx.x;      // 0..63
    int bc    = blockIdx.y;      // 0..BB*CC-1
    size_t base = (size_t)bc * NN + chunk * 1024;
    float s = 0.f;
    #pragma unroll
    for (int i = 0; i < 4; i++) s += y[base + i*256 + threadIdx.x];
    __shared__ float red[256];
    red[threadIdx.x] = s; __syncthreads();
    for (int off = 128; off; off >>= 1) {
        if (threadIdx.x < off) red[threadIdx.x] += red[threadIdx.x + off];
        __syncthreads();
    }
    if (threadIdx.x == 0) part[bc*64 + chunk] = red[0];
}

// ---------------- mean stage2 + sca 1x1 conv ----------------
__global__ void xsca_kernel(const float* __restrict__ part, const float* __restrict__ sw,
                            const float* __restrict__ sb, float* __restrict__ xsca)
{
    __shared__ float m[CC];
    int b = blockIdx.x, c = threadIdx.x;
    float s = 0.f;
    for (int k = 0; k < 64; k++) s += part[(b*CC + c)*64 + k];
    m[c] = s * (1.f / NN);
    __syncthreads();
    float a = __ldg(&sb[c]);
    for (int i = 0; i < CC; i++) a += __ldg(&sw[c*CC + i]) * m[i];
    xsca[b*CC + c] = a;
}

// ---------------- generic 1x1 conv (GEMM), optional residual (channel-first buffer) ----------------
template<int INC, int OUT, int RESID>
__global__ void conv1x1_kernel(const float* __restrict__ in, const float* __restrict__ w,
                               float* __restrict__ out, const float* __restrict__ resid)
{
    __shared__ float yt[INC][64];
    int b  = blockIdx.y;
    int n0 = blockIdx.x * 64;
    const float* inb = in + (size_t)b * INC * NN + n0;
    for (int idx = threadIdx.x; idx < INC * 64; idx += 256) {
        int c = idx >> 6, p = idx & 63;
        yt[c][p] = inb[(size_t)c * NN + p];
    }
    __syncthreads();
    int pxg = threadIdx.x & 15;   // 16 pixel groups of 4
    int og  = threadIdx.x >> 4;   // 16 output groups
    for (int ob = og * 4; ob < OUT; ob += 64) {
        float acc[4][4] = {};
        for (int c = 0; c < INC; c++) {
            float4 yv = *reinterpret_cast<const float4*>(&yt[c][pxg * 4]);
            #pragma unroll
            for (int j = 0; j < 4; j++) {
                int o = ob + j;
                float wv = ((OUT % 64 == 0) || o < OUT) ? __ldg(&w[(size_t)o*INC + c]) : 0.f;
                acc[j][0] += wv * yv.x; acc[j][1] += wv * yv.y;
                acc[j][2] += wv * yv.z; acc[j][3] += wv * yv.w;
            }
        }
        #pragma unroll
        for (int j = 0; j < 4; j++) {
            int o = ob + j;
            if ((OUT % 64 != 0) && o >= OUT) break;
            size_t base = ((size_t)b*OUT + o)*NN + n0 + pxg*4;
            float4 r = make_float4(acc[j][0], acc[j][1], acc[j][2], acc[j][3]);
            if (RESID == 1) {
                float4 rr = *reinterpret_cast<const float4*>(&resid[base]);
                r.x += rr.x; r.y += rr.y; r.z += rr.z; r.w += rr.w;
            }
            *reinterpret_cast<float4*>(&out[base]) = r;
        }
    }
}

// ---------------- depthwise 3x3 (pad 1) ----------------
template<int NCH>
__global__ void dw3_kernel(const float* __restrict__ in, const float* __restrict__ w,
                           float* __restrict__ out)
{
    int z = blockIdx.z; int b = z / NCH; int ch = z % NCH;
    const float* plane = in + ((size_t)b*NCH + ch) * NN;
    __shared__ float s[10][34];
    int tx = threadIdx.x & 31, ty = threadIdx.x >> 5;
    int gx0 = blockIdx.x * 32, gy0 = blockIdx.y * 8;
    for (int idx = threadIdx.x; idx < 340; idx += 256) {
        int r = idx / 34, c = idx % 34;
        int gy = gy0 - 1 + r, gx = gx0 - 1 + c;
        s[r][c] = (gy >= 0 && gy < HH && gx >= 0 && gx < WW) ? plane[gy*WW + gx] : 0.f;
    }
    __syncthreads();
    float acc = 0.f;
    #pragma unroll
    for (int ky = 0; ky < 3; ky++)
        #pragma unroll
        for (int kx = 0; kx < 3; kx++)
            acc += __ldg(&w[ch*9 + ky*3 + kx]) * s[ty + ky][tx + kx];
    out[((size_t)b*NCH + ch)*NN + (gy0 + ty)*WW + gx0 + tx] = acc;
}

// ---------------- grouped conv (groups=C, 2 in / 1 out per group) + GELU ----------------
__global__ void dw2gelu_kernel(const float* __restrict__ u, const float* __restrict__ w,
                               float* __restrict__ g1)
{
    int z = blockIdx.z; int b = z / CC; int c = z % CC;
    __shared__ float s[2][10][34];
    int tx = threadIdx.x & 31, ty = threadIdx.x >> 5;
    int gx0 = blockIdx.x * 32, gy0 = blockIdx.y * 8;
    for (int idx = threadIdx.x; idx < 680; idx += 256) {
        int j = idx / 340; int rem = idx % 340;
        int r = rem / 34, cc = rem % 34;
        int gy = gy0 - 1 + r, gx = gx0 - 1 + cc;
        s[j][r][cc] = (gy >= 0 && gy < HH && gx >= 0 && gx < WW)
                      ? u[((size_t)b*C2 + 2*c + j)*NN + gy*WW + gx] : 0.f;
    }
    __syncthreads();
    float acc = 0.f;
    #pragma unroll
    for (int j = 0; j < 2; j++)
        #pragma unroll
        for (int ky = 0; ky < 3; ky++)
            #pragma unroll
            for (int kx = 0; kx < 3; kx++)
                acc += __ldg(&w[(c*2 + j)*9 + ky*3 + kx]) * s[j][ty + ky][tx + kx];
    g1[((size_t)b*CC + c)*NN + (gy0 + ty)*WW + gx0 + tx] = gelu_exact(acc);
}

// ---------------- FFN depthwise 3x3 + gated GELU fusion ----------------
__global__ void ffndw_kernel(const float* __restrict__ h, const float* __restrict__ w,
                             float* __restrict__ g2)
{
    int z = blockIdx.z; int b = z / HIDD; int i = z % HIDD;
    const float* p0 = h + ((size_t)b*HID2 + i) * NN;
    const float* p1 = h + ((size_t)b*HID2 + HIDD + i) * NN;
    __shared__ float s[2][10][34];
    int tx = threadIdx.x & 31, ty = threadIdx.x >> 5;
    int gx0 = blockIdx.x * 32, gy0 = blockIdx.y * 8;
    for (int idx = threadIdx.x; idx < 680; idx += 256) {
        int j = idx / 340; int rem = idx % 340;
        int r = rem / 34, cc = rem % 34;
        int gy = gy0 - 1 + r, gx = gx0 - 1 + cc;
        const float* pl = j ? p1 : p0;
        s[j][r][cc] = (gy >= 0 && gy < HH && gx >= 0 && gx < WW) ? pl[gy*WW + gx] : 0.f;
    }
    __syncthreads();
    float a0 = 0.f, a1 = 0.f;
    #pragma unroll
    for (int ky = 0; ky < 3; ky++)
        #pragma unroll
        for (int kx = 0; kx < 3; kx++) {
            float sv0 = s[0][ty + ky][tx + kx];
            float sv1 = s[1][ty + ky][tx + kx];
            a0 += __ldg(&w[i*9 + ky*3 + kx]) * sv0;
            a1 += __ldg(&w[(HIDD + i)*9 + ky*3 + kx]) * sv1;
        }
    g2[((size_t)b*HIDD + i)*NN + (gy0 + ty)*WW + gx0 + tx] = gelu_exact(a0) * a1;
}

// ---------------- per-pixel q/k L2 normalization (in-place) ----------------
__global__ void qknorm_kernel(float* __restrict__ qkv)
{
    int gid = blockIdx.x * 256 + threadIdx.x;
    int b = gid >> 16;
    int n = gid & (NN - 1);
    #pragma unroll
    for (int hh = 0; hh < HEADS; hh++) {
        size_t qb = ((size_t)b*C3 + hh*CHD)*NN + n;
        size_t kb = ((size_t)b*C3 + CC + hh*CHD)*NN + n;
        float q[8], k[8]; float qs = 0.f, ks = 0.f;
        #pragma unroll
        for (int i = 0; i < 8; i++) {
            q[i] = qkv[qb + i*NN]; qs += q[i]*q[i];
            k[i] = qkv[kb + i*NN]; ks += k[i]*k[i];
        }
        float qi = 1.f / (sqrtf(qs) + 1e-6f);
        float ki = 1.f / (sqrtf(ks) + 1e-6f);
        #pragma unroll
        for (int i = 0; i < 8; i++) {
            qkv[qb + i*NN] = q[i]*qi;
            qkv[kb + i*NN] = k[i]*ki;
        }
    }
}

// ---------------- attention reductions (k@v, ksum, vsum) stage1 ----------------
__global__ void attnred1_kernel(const float* __restrict__ qkv, float* __restrict__ part)
{
    int bh = blockIdx.y; int b = bh >> 3; int hh = bh & 7;
    int chunk = blockIdx.x;
    size_t kb = ((size_t)b*C3 + CC + hh*CHD)*NN;
    size_t vb = ((size_t)b*C3 + 2*CC + hh*CHD)*NN;
    float kv[8][8]; float ks[8]; float vs[8];
    #pragma unroll
    for (int i = 0; i < 8; i++) {
        ks[i] = 0.f; vs[i] = 0.f;
        #pragma unroll
        for (int j = 0; j < 8; j++) kv[i][j] = 0.f;
    }
    for (int it = 0; it < 4; it++) {
        int n = chunk*1024 + it*256 + threadIdx.x;
        float kk[8], vv[8];
        #pragma unroll
        for (int i = 0; i < 8; i++) { kk[i] = qkv[kb + i*NN + n]; vv[i] = qkv[vb + i*NN + n]; }
        #pragma unroll
        for (int i = 0; i < 8; i++) {
            ks[i] += kk[i]; vs[i] += vv[i];
            #pragma unroll
            for (int j = 0; j < 8; j++) kv[i][j] += kk[i]*vv[j];
        }
    }
    __shared__ float red[8][80];
    int lane = threadIdx.x & 31, wid = threadIdx.x >> 5;
    #pragma unroll
    for (int idx = 0; idx < 80; idx++) {
        float v;
        if (idx < 64) v = kv[idx >> 3][idx & 7];
        else if (idx < 72) v = ks[idx - 64];
        else v = vs[idx - 72];
        #pragma unroll
        for (int off = 16; off; off >>= 1) v += __shfl_down_sync(0xffffffffu, v, off);
        if (lane == 0) red[wid][idx] = v;
    }
    __syncthreads();
    if (threadIdx.x < 80) {
        float s = 0.f;
        #pragma unroll
        for (int w2 = 0; w2 < 8; w2++) s += red[w2][threadIdx.x];
        part[((size_t)bh*64 + chunk)*80 + threadIdx.x] = s;
    }
}

__global__ void attnred2_kernel(const float* __restrict__ part, float* __restrict__ attnm)
{
    int bh = blockIdx.x; int t = threadIdx.x;
    if (t < 80) {
        float s = 0.f;
        for (int c2 = 0; c2 < 64; c2++) s += part[((size_t)bh*64 + c2)*80 + t];
        attnm[bh*80 + t] = s;
    }
}

// ---------------- multi-window refine conv + sigmoid ----------------
__global__ void refine_kernel(const float* __restrict__ qkv,
    const float* __restrict__ r3w, const float* __restrict__ r3b,
    const float* __restrict__ r5w, const float* __restrict__ r5b,
    const float* __restrict__ r7w, const float* __restrict__ r7b,
    float* __restrict__ refine)
{
    int z = blockIdx.z; int b = z >> 3; int hh = z & 7;
    int ws; const float* wp; float bias;
    if (hh < 2)       { ws = 3; wp = r3w + hh*16*9;       bias = __ldg(&r3b[hh]); }
    else if (hh < 5)  { ws = 5; wp = r5w + (hh-2)*16*25;  bias = __ldg(&r5b[hh-2]); }
    else              { ws = 7; wp = r7w + (hh-5)*16*49;  bias = __ldg(&r7b[hh-5]); }
    int r = ws >> 1;
    __shared__ float s[14][38];
    int tx = threadIdx.x & 31, ty = threadIdx.x >> 5;
    int gx0 = blockIdx.x * 32, gy0 = blockIdx.y * 8;
    int TW = 32 + 2*r, TH = 8 + 2*r, tot = TW*TH;
    float acc = 0.f;
    for (int ci = 0; ci < 16; ci++) {
        int chan = (ci < 8) ? (hh*CHD + ci) : (CC + hh*CHD + ci - 8);
        const float* plane = qkv + ((size_t)b*C3 + chan)*NN;
        __syncthreads();
        for (int idx = threadIdx.x; idx < tot; idx += 256) {
            int rr = idx / TW, cc2 = idx % TW;
            int gy = gy0 - r + rr, gx = gx0 - r + cc2;
            s[rr][cc2] = (gy >= 0 && gy < HH && gx >= 0 && gx < WW) ? plane[gy*WW + gx] : 0.f;
        }
        __syncthreads();
        const float* wc = wp + ci*ws*ws;
        for (int ky = 0; ky < ws; ky++)
            for (int kx = 0; kx < ws; kx++)
                acc += __ldg(&wc[ky*ws + kx]) * s[ty + ky][tx + kx];
    }
    float val = acc + bias;
    refine[(size_t)z*NN + (gy0 + ty)*WW + gx0 + tx] = 1.f / (1.f + expf(-val));
}

// ---------------- combine: linear attention epilogue * refine * xsca * gelu(x1) ----------------
__global__ void combine_kernel(const float* __restrict__ qkv, const float* __restrict__ attnm,
                               const float* __restrict__ refine, const float* __restrict__ g1,
                               const float* __restrict__ xsca, const float* __restrict__ temp,
                               float* __restrict__ comb)
{
    int z = blockIdx.y; int b = z >> 3; int hh = z & 7;
    __shared__ float am[80];
    if (threadIdx.x < 80) am[threadIdx.x] = attnm[z*80 + threadIdx.x];
    __syncthreads();
    int n = blockIdx.x * 256 + threadIdx.x;
    float q[8];
    size_t qb = ((size_t)b*C3 + hh*CHD)*NN + n;
    #pragma unroll
    for (int i = 0; i < 8; i++) q[i] = qkv[qb + i*NN];
    float den = (float)NN + 1e-6f;
    #pragma unroll
    for (int i = 0; i < 8; i++) den += q[i]*am[64 + i];
    float scale = __ldg(&temp[hh]) * refine[(size_t)z*NN + n] / den;
    #pragma unroll
    for (int j = 0; j < 8; j++) {
        float num = am[72 + j];
        #pragma unroll
        for (int i = 0; i < 8; i++) num += q[i]*am[i*8 + j];
        int c = hh*CHD + j;
        size_t o = ((size_t)b*CC + c)*NN + n;
        comb[o] = num * scale * __ldg(&xsca[b*CC + c]) * g1[o];
    }
}

// ---------------- launch ----------------
extern "C" void kernel_launch(void* const* d_in, const int* in_sizes, int n_in,
                              void* d_out, int out_size)
{
    const float* x      = (const float*)d_in[0];
    const float* ln1_w  = (const float*)d_in[1];
    const float* sca_w  = (const float*)d_in[2];
    const float* sca_b  = (const float*)d_in[3];
    const float* dw1_w  = (const float*)d_in[4];
    const float* dw2_w  = (const float*)d_in[5];
    const float* qkv_w  = (const float*)d_in[6];
    const float* qkv_dw = (const float*)d_in[7];
    const float* temp   = (const float*)d_in[8];
    const float* r3_w   = (const float*)d_in[9];
    const float* r3_b   = (const float*)d_in[10];
    const float* r5_w   = (const float*)d_in[11];
    const float* r5_b   = (const float*)d_in[12];
    const float* r7_w   = (const float*)d_in[13];
    const float* r7_b   = (const float*)d_in[14];
    const float* proj_w = (const float*)d_in[15];
    const float* ln2_w  = (const float*)d_in[16];
    const float* pin_w  = (const float*)d_in[17];
    const float* ffn_dw = (const float*)d_in[18];
    const float* pout_w = (const float*)d_in[19];
    float* out = (float*)d_out;

    float *py, *pxT, *pxi1, *pg1, *pbig, *pqkv, *pu, *pg2, *pref, *pmp, *pxsca, *ppart, *pattnm;
    cudaGetSymbolAddress((void**)&py,    d_y);
    cudaGetSymbolAddress((void**)&pxT,   d_xT);
    cudaGetSymbolAddress((void**)&pxi1,  d_xi1);
    cudaGetSymbolAddress((void**)&pg1,   d_g1);
    cudaGetSymbolAddress((void**)&pbig,  d_big);
    cudaGetSymbolAddress((void**)&pqkv,  d_qkv);
    cudaGetSymbolAddress((void**)&pu,    d_u);
    cudaGetSymbolAddress((void**)&pg2,   d_g2);
    cudaGetSymbolAddress((void**)&pref,  d_ref);
    cudaGetSymbolAddress((void**)&pmp,   d_meanpart);
    cudaGetSymbolAddress((void**)&pxsca, d_xsca);
    cudaGetSymbolAddress((void**)&ppart, d_attnpart);
    cudaGetSymbolAddress((void**)&pattnm,d_attnm);

    // LN1 (+ transpose of input for residual)
    ln_kernel<0><<<BN/256, 256>>>(x, ln1_w, py, pxT);
    // channel mean of LN output -> xsca
    mean1_kernel<<<dim3(64, BB*CC), 256>>>(py, pmp);
    xsca_kernel<<<BB, CC>>>(pmp, sca_w, sca_b, pxsca);
    // 1x1 convs: qkv (192ch) and dw1 (128ch)
    conv1x1_kernel<CC, C3, 0><<<dim3(NN/64, BB), 256>>>(py, qkv_w, pbig, nullptr);
    conv1x1_kernel<CC, C2, 0><<<dim3(NN/64, BB), 256>>>(py, dw1_w, pu, nullptr);
    // depthwise 3x3 on qkv
    dw3_kernel<C3><<<dim3(WW/32, HH/8, BB*C3), 256>>>(pbig, qkv_dw, pqkv);
    // grouped conv dw2 + gelu -> g1
    dw2gelu_kernel<<<dim3(WW/32, HH/8, BB*CC), 256>>>(pu, dw2_w, pg1);
    // normalize q,k per pixel in-place
    qknorm_kernel<<<BN/256, 256>>>(pqkv);
    // global reductions k@v, ksum, vsum (deterministic 2-stage)
    attnred1_kernel<<<dim3(64, 32), 256>>>(pqkv, ppart);
    attnred2_kernel<<<32, 128>>>(ppart, pattnm);
    // refine conv + sigmoid
    refine_kernel<<<dim3(WW/32, HH/8, BB*HEADS), 256>>>(pqkv, r3_w, r3_b, r5_w, r5_b, r7_w, r7_b, pref);
    // combine -> comb (reuse d_y)
    combine_kernel<<<dim3(NN/256, BB*HEADS), 256>>>(pqkv, pattnm, pref, pg1, pxsca, temp, py);
    // proj 1x1 + residual (from transposed input)
    conv1x1_kernel<CC, CC, 1><<<dim3(NN/64, BB), 256>>>(py, proj_w, pxi1, pxT);
    // LN2 (reuse d_y as output)
    ln_kernel<1><<<BN/256, 256>>>(pxi1, ln2_w, py, nullptr);
    // FFN: pin 64->340
    conv1x1_kernel<CC, HID2, 0><<<dim3(NN/64, BB), 256>>>(py, pin_w, pbig, nullptr);
    // FFN depthwise + gated gelu
    ffndw_kernel<<<dim3(WW/32, HH/8, BB*HIDD), 256>>>(pbig, ffn_dw, pg2);
    // pout 170->64 + residual -> output
    conv1x1_kernel<HIDD, CC, 1><<<dim3(NN/64, BB), 256>>>(pg2, pout_w, out, pxi1);
}

// round 5
// speedup vs baseline: 1.4174x; 1.4174x over previous
#include <cuda_runtime.h>
#include <math.h>

// ---------------- constants ----------------
#define BB   4
#define CC   64
#define HH   256
#define WW   256
#define NN   65536      // HH*WW
#define HEADS 8
#define CHD  8
#define HIDD 170
#define HID2 340
#define C3   192
#define C2   128
#define BN   262144     // BB*NN

// ---------------- scratch (static device memory; allocation-free) ----------------
__device__ float d_y   [BB*CC*NN];     // LN1 out -> comb -> LN2 out (reused)
__device__ float d_xT  [BB*CC*NN];     // input transposed to (B,C,N)
__device__ float d_xi1 [BB*CC*NN];     // after attention residual
__device__ float d_g1  [BB*CC*NN];     // gelu(x1)
__device__ float d_big [BB*HID2*NN];   // qkv_pre (192ch) then FFN hidden (340ch)
__device__ float d_qkv [BB*C3*NN];     // depthwise qkv (raw; norms fused into consumers)
__device__ float d_u   [BB*C2*NN];     // dw1 out (128ch)
__device__ float d_g2  [BB*HIDD*NN];   // gated FFN hidden (170ch)
__device__ float d_ref [BB*HEADS*NN];  // sigmoid(refine)
__device__ float d_meanpart[BB*CC*64];
__device__ float d_xsca[BB*CC];
__device__ float d_attnpart[32*64*80];
__device__ float d_attnm[32*80];

__device__ __forceinline__ float gelu_exact(float x) {
    return 0.5f * x * (1.f + erff(x * 0.70710678118654752f));
}

// warp mapping: 4 rows x 8 col-groups per warp -> conflict-free LDS.128 on 40-float rows
__device__ __forceinline__ void tmap(int tid, int& row, int& cg) {
    int lane = tid & 31;
    cg  = lane & 7;
    row = ((tid >> 5) << 2) | ((lane >> 3) & 3);
}

// ---------------- BiasFree LayerNorm ----------------
template<int LAYOUT>
__global__ void ln_kernel(const float* __restrict__ in, const float* __restrict__ w,
                          float* __restrict__ out, float* __restrict__ xT)
{
    int gid = blockIdx.x * 256 + threadIdx.x;
    int b = gid >> 16;
    int n = gid & (NN - 1);
    float v[CC];
    if (LAYOUT == 0) {
        const float4* p = reinterpret_cast<const float4*>(in + (size_t)gid * CC);
        #pragma unroll
        for (int i = 0; i < 16; i++) {
            float4 t = p[i];
            v[4*i] = t.x; v[4*i+1] = t.y; v[4*i+2] = t.z; v[4*i+3] = t.w;
        }
    } else {
        #pragma unroll
        for (int c = 0; c < CC; c++) v[c] = in[((size_t)b*CC + c)*NN + n];
    }
    float s = 0.f, s2 = 0.f;
    #pragma unroll
    for (int c = 0; c < CC; c++) { s += v[c]; s2 += v[c]*v[c]; }
    float mean = s * (1.f / CC);
    float var  = s2 * (1.f / CC) - mean * mean;
    float inv  = rsqrtf(var + 1e-5f);
    #pragma unroll
    for (int c = 0; c < CC; c++) {
        size_t o = ((size_t)b*CC + c)*NN + n;
        out[o] = v[c] * inv * __ldg(&w[c]);
        if (LAYOUT == 0) xT[o] = v[c];
    }
}

// ---------------- channel mean of LN1 output (stage 1) ----------------
__global__ void mean1_kernel(const float* __restrict__ y, float* __restrict__ part)
{
    int chunk = blockIdx.x;
    int bc    = blockIdx.y;
    size_t base = (size_t)bc * NN + chunk * 1024;
    float s = 0.f;
    #pragma unroll
    for (int i = 0; i < 4; i++) s += y[base + i*256 + threadIdx.x];
    __shared__ float red[256];
    red[threadIdx.x] = s; __syncthreads();
    for (int off = 128; off; off >>= 1) {
        if (threadIdx.x < off) red[threadIdx.x] += red[threadIdx.x + off];
        __syncthreads();
    }
    if (threadIdx.x == 0) part[bc*64 + chunk] = red[0];
}

__global__ void xsca_kernel(const float* __restrict__ part, const float* __restrict__ sw,
                            const float* __restrict__ sb, float* __restrict__ xsca)
{
    __shared__ float m[CC];
    int b = blockIdx.x, c = threadIdx.x;
    float s = 0.f;
    for (int k = 0; k < 64; k++) s += part[(b*CC + c)*64 + k];
    m[c] = s * (1.f / NN);
    __syncthreads();
    float a = __ldg(&sb[c]);
    for (int i = 0; i < CC; i++) a += __ldg(&sw[c*CC + i]) * m[i];
    xsca[b*CC + c] = a;
}

// ---------------- register-tiled 1x1 conv GEMM ----------------
// block: 128 pixels x 64 outputs; thread: 8 outputs x 4 pixels.
// warp wi -> outputs [o0+wi*8, +8); lane -> pixels [n0+lane*4, +4).
template<int INC, int OUT, int RESID>
__global__ void __launch_bounds__(256) conv1x1_kernel(
        const float* __restrict__ in, const float* __restrict__ w,
        float* __restrict__ out, const float* __restrict__ resid)
{
    __shared__ float in_s[64][128];
    __shared__ float w_s[64][64];
    int b  = blockIdx.z;
    int n0 = blockIdx.x * 128;
    int o0 = blockIdx.y * 64;
    int wi = threadIdx.x >> 5, lane = threadIdx.x & 31;
    float acc[8][4];
    #pragma unroll
    for (int j = 0; j < 8; j++)
        #pragma unroll
        for (int p = 0; p < 4; p++) acc[j][p] = 0.f;

    for (int k0 = 0; k0 < INC; k0 += 64) {
        const int kc = (INC - k0 >= 64) ? 64 : (INC - k0);
        __syncthreads();
        for (int idx = threadIdx.x; idx < kc*32; idx += 256) {
            int k = idx >> 5, p = idx & 31;
            *(float4*)&in_s[k][p*4] =
                *(const float4*)&in[((size_t)(b*INC + k0 + k))*NN + n0 + p*4];
        }
        if (kc < 64) {
            for (int idx = threadIdx.x; idx < (64-kc)*32; idx += 256) {
                int k = kc + (idx >> 5), p = idx & 31;
                *(float4*)&in_s[k][p*4] = make_float4(0.f,0.f,0.f,0.f);
            }
        }
        for (int idx = threadIdx.x; idx < 64*64; idx += 256) {
            int o = idx >> 6, k = idx & 63;
            int oo = o0 + o;
            float wv = 0.f;
            if (((OUT % 64 == 0) || oo < OUT) && k < kc)
                wv = w[(size_t)oo*INC + k0 + k];
            w_s[o][k] = wv;
        }
        __syncthreads();
        #pragma unroll 2
        for (int k4 = 0; k4 < 16; k4++) {
            float4 wv[8];
            #pragma unroll
            for (int j = 0; j < 8; j++) wv[j] = *(float4*)&w_s[wi*8+j][k4*4];
            #pragma unroll
            for (int kk = 0; kk < 4; kk++) {
                float4 xv = *(float4*)&in_s[k4*4+kk][lane*4];
                #pragma unroll
                for (int j = 0; j < 8; j++) {
                    float ww = (kk==0)?wv[j].x:(kk==1)?wv[j].y:(kk==2)?wv[j].z:wv[j].w;
                    acc[j][0] += ww*xv.x; acc[j][1] += ww*xv.y;
                    acc[j][2] += ww*xv.z; acc[j][3] += ww*xv.w;
                }
            }
        }
    }
    #pragma unroll
    for (int j = 0; j < 8; j++) {
        int oo = o0 + wi*8 + j;
        if ((OUT % 64 != 0) && oo >= OUT) break;
        size_t base = ((size_t)(b*OUT + oo))*NN + n0 + lane*4;
        float4 r = make_float4(acc[j][0],acc[j][1],acc[j][2],acc[j][3]);
        if (RESID) {
            float4 rr = *(const float4*)&resid[base];
            r.x += rr.x; r.y += rr.y; r.z += rr.z; r.w += rr.w;
        }
        *(float4*)&out[base] = r;
    }
}

// ---------------- depthwise 3x3 (pad 1), 32x32 tile, 4 cols/thread ----------------
template<int NCH>
__global__ void dw3_kernel(const float* __restrict__ in, const float* __restrict__ w,
                           float* __restrict__ out)
{
    int z = blockIdx.z; int b = z / NCH; int ch = z - b*NCH;
    const float* plane = in + ((size_t)b*NCH + ch) * NN;
    __shared__ float raw[34*40];
    int row, cg; tmap(threadIdx.x, row, cg);
    int gx0 = blockIdx.x * 32, gy0 = blockIdx.y * 32;
    for (int idx = threadIdx.x; idx < 34*34; idx += 256) {
        int r = idx / 34, c = idx - r*34;
        int gy = gy0 - 1 + r, gx = gx0 - 1 + c;
        raw[r*40 + c] = (gy >= 0 && gy < HH && gx >= 0 && gx < WW) ? plane[gy*WW + gx] : 0.f;
    }
    float wr[9];
    #pragma unroll
    for (int i = 0; i < 9; i++) wr[i] = __ldg(&w[ch*9 + i]);
    __syncthreads();
    float acc[4] = {0.f,0.f,0.f,0.f};
    #pragma unroll
    for (int ky = 0; ky < 3; ky++) {
        const float4* rp = (const float4*)&raw[(row+ky)*40 + cg*4];
        float f[8];
        *(float4*)&f[0] = rp[0]; *(float4*)&f[4] = rp[1];
        #pragma unroll
        for (int kx = 0; kx < 3; kx++)
            #pragma unroll
            for (int cx = 0; cx < 4; cx++) acc[cx] += wr[ky*3+kx]*f[cx+kx];
    }
    size_t o = ((size_t)b*NCH + ch)*NN + (size_t)(gy0+row)*WW + gx0 + cg*4;
    *(float4*)&out[o] = make_float4(acc[0],acc[1],acc[2],acc[3]);
}

// ---------------- grouped conv dw2 (2 in / 1 out per group) + GELU ----------------
__global__ void dw2gelu_kernel(const float* __restrict__ u, const float* __restrict__ w,
                               float* __restrict__ g1)
{
    int z = blockIdx.z; int b = z / CC; int c = z - b*CC;
    __shared__ float raw[2][34*40];
    int row, cg; tmap(threadIdx.x, row, cg);
    int gx0 = blockIdx.x * 32, gy0 = blockIdx.y * 32;
    for (int idx = threadIdx.x; idx < 2*34*34; idx += 256) {
        int j = idx / (34*34); int rem = idx - j*34*34;
        int r = rem / 34, cc2 = rem - r*34;
        int gy = gy0 - 1 + r, gx = gx0 - 1 + cc2;
        raw[j][r*40 + cc2] = (gy >= 0 && gy < HH && gx >= 0 && gx < WW)
                             ? u[((size_t)b*C2 + 2*c + j)*NN + gy*WW + gx] : 0.f;
    }
    float wr[2][9];
    #pragma unroll
    for (int j = 0; j < 2; j++)
        #pragma unroll
        for (int i = 0; i < 9; i++) wr[j][i] = __ldg(&w[(c*2 + j)*9 + i]);
    __syncthreads();
    float acc[4] = {0.f,0.f,0.f,0.f};
    #pragma unroll
    for (int j = 0; j < 2; j++)
        #pragma unroll
        for (int ky = 0; ky < 3; ky++) {
            const float4* rp = (const float4*)&raw[j][(row+ky)*40 + cg*4];
            float f[8];
            *(float4*)&f[0] = rp[0]; *(float4*)&f[4] = rp[1];
            #pragma unroll
            for (int kx = 0; kx < 3; kx++)
                #pragma unroll
                for (int cx = 0; cx < 4; cx++) acc[cx] += wr[j][ky*3+kx]*f[cx+kx];
        }
    size_t o = ((size_t)b*CC + c)*NN + (size_t)(gy0+row)*WW + gx0 + cg*4;
    *(float4*)&g1[o] = make_float4(gelu_exact(acc[0]),gelu_exact(acc[1]),
                                   gelu_exact(acc[2]),gelu_exact(acc[3]));
}

// ---------------- FFN depthwise 3x3 + gated GELU ----------------
__global__ void ffndw_kernel(const float* __restrict__ h, const float* __restrict__ w,
                             float* __restrict__ g2)
{
    int z = blockIdx.z; int b = z / HIDD; int i = z - b*HIDD;
    const float* p0 = h + ((size_t)b*HID2 + i) * NN;
    const float* p1 = h + ((size_t)b*HID2 + HIDD + i) * NN;
    __shared__ float raw[2][34*40];
    int row, cg; tmap(threadIdx.x, row, cg);
    int gx0 = blockIdx.x * 32, gy0 = blockIdx.y * 32;
    for (int idx = threadIdx.x; idx < 2*34*34; idx += 256) {
        int j = idx / (34*34); int rem = idx - j*34*34;
        int r = rem / 34, cc2 = rem - r*34;
        int gy = gy0 - 1 + r, gx = gx0 - 1 + cc2;
        const float* pl = j ? p1 : p0;
        raw[j][r*40 + cc2] = (gy >= 0 && gy < HH && gx >= 0 && gx < WW) ? pl[gy*WW + gx] : 0.f;
    }
    float w0[9], w1[9];
    #pragma unroll
    for (int t = 0; t < 9; t++) { w0[t] = __ldg(&w[i*9 + t]); w1[t] = __ldg(&w[(HIDD+i)*9 + t]); }
    __syncthreads();
    float a0[4] = {0.f,0.f,0.f,0.f}, a1[4] = {0.f,0.f,0.f,0.f};
    #pragma unroll
    for (int ky = 0; ky < 3; ky++) {
        const float4* rp0 = (const float4*)&raw[0][(row+ky)*40 + cg*4];
        const float4* rp1 = (const float4*)&raw[1][(row+ky)*40 + cg*4];
        float f0[8], f1[8];
        *(float4*)&f0[0] = rp0[0]; *(float4*)&f0[4] = rp0[1];
        *(float4*)&f1[0] = rp1[0]; *(float4*)&f1[4] = rp1[1];
        #pragma unroll
        for (int kx = 0; kx < 3; kx++)
            #pragma unroll
            for (int cx = 0; cx < 4; cx++) {
                a0[cx] += w0[ky*3+kx]*f0[cx+kx];
                a1[cx] += w1[ky*3+kx]*f1[cx+kx];
            }
    }
    size_t o = ((size_t)b*HIDD + i)*NN + (size_t)(gy0+row)*WW + gx0 + cg*4;
    *(float4*)&g2[o] = make_float4(gelu_exact(a0[0])*a1[0], gelu_exact(a0[1])*a1[1],
                                   gelu_exact(a0[2])*a1[2], gelu_exact(a0[3])*a1[3]);
}

// ---------------- attention reductions (k@v, ksum, vsum) with fused k-norm ----------------
__global__ void attnred1_kernel(const float* __restrict__ qkv, float* __restrict__ part)
{
    int bh = blockIdx.y; int b = bh >> 3; int hh = bh & 7;
    int chunk = blockIdx.x;
    size_t kb = ((size_t)b*C3 + CC + hh*CHD)*NN;
    size_t vb = ((size_t)b*C3 + 2*CC + hh*CHD)*NN;
    float kv[8][8]; float ks[8]; float vs[8];
    #pragma unroll
    for (int i = 0; i < 8; i++) {
        ks[i] = 0.f; vs[i] = 0.f;
        #pragma unroll
        for (int j = 0; j < 8; j++) kv[i][j] = 0.f;
    }
    for (int it = 0; it < 4; it++) {
        int n = chunk*1024 + it*256 + threadIdx.x;
        float kk[8], vv[8]; float ks2 = 0.f;
        #pragma unroll
        for (int i = 0; i < 8; i++) {
            kk[i] = qkv[kb + i*NN + n]; ks2 += kk[i]*kk[i];
            vv[i] = qkv[vb + i*NN + n];
        }
        float ksc = 1.f / (sqrtf(ks2) + 1e-6f);
        #pragma unroll
        for (int i = 0; i < 8; i++) {
            kk[i] *= ksc;
            ks[i] += kk[i]; vs[i] += vv[i];
            #pragma unroll
            for (int j = 0; j < 8; j++) kv[i][j] += kk[i]*vv[j];
        }
    }
    __shared__ float red[8][80];
    int lane = threadIdx.x & 31, wid = threadIdx.x >> 5;
    #pragma unroll
    for (int idx = 0; idx < 80; idx++) {
        float v;
        if (idx < 64) v = kv[idx >> 3][idx & 7];
        else if (idx < 72) v = ks[idx - 64];
        else v = vs[idx - 72];
        #pragma unroll
        for (int off = 16; off; off >>= 1) v += __shfl_down_sync(0xffffffffu, v, off);
        if (lane == 0) red[wid][idx] = v;
    }
    __syncthreads();
    if (threadIdx.x < 80) {
        float s = 0.f;
        #pragma unroll
        for (int w2 = 0; w2 < 8; w2++) s += red[w2][threadIdx.x];
        part[((size_t)bh*64 + chunk)*80 + threadIdx.x] = s;
    }
}

__global__ void attnred2_kernel(const float* __restrict__ part, float* __restrict__ attnm)
{
    int bh = blockIdx.x; int t = threadIdx.x;
    if (t < 80) {
        float s = 0.f;
        for (int c2 = 0; c2 < 64; c2++) s += part[((size_t)bh*64 + c2)*80 + t];
        attnm[bh*80 + t] = s;
    }
}

// ---------------- multi-window refine conv + sigmoid (fused q/k norm) ----------------
template<int WS>
__global__ void refine_kernel(const float* __restrict__ qkv, const float* __restrict__ w,
                              const float* __restrict__ bias, int head0, int nh,
                              float* __restrict__ refine)
{
    constexpr int R  = WS/2;
    constexpr int RR = 32 + 2*R;
    constexpr int PS = RR*40;
    extern __shared__ float sm[];
    float* wsm = sm + 16*PS;
    int z = blockIdx.z; int b = z / nh; int hw = z - b*nh; int hh = head0 + hw;
    int row, cg; tmap(threadIdx.x, row, cg);
    int gx0 = blockIdx.x*32, gy0 = blockIdx.y*32;
    // load 16 planes (8 q + 8 k) raw
    for (int idx = threadIdx.x; idx < 16*RR*RR; idx += 256) {
        int ci = idx / (RR*RR); int rem = idx - ci*RR*RR;
        int r = rem / RR, c = rem - r*RR;
        int gy = gy0 - R + r, gx = gx0 - R + c;
        int chan = (ci < 8) ? (hh*CHD + ci) : (CC + hh*CHD + ci - 8);
        sm[ci*PS + r*40 + c] = (gy >= 0 && gy < HH && gx >= 0 && gx < WW)
                               ? qkv[((size_t)b*C3 + chan)*NN + gy*WW + gx] : 0.f;
    }
    for (int idx = threadIdx.x; idx < 16*WS*WS; idx += 256)
        wsm[idx] = __ldg(&w[hw*16*WS*WS + idx]);
    __syncthreads();
    // normalize q (ci 0-7) and k (ci 8-15) per pixel
    for (int p = threadIdx.x; p < RR*RR; p += 256) {
        int r = p / RR, c = p - r*RR;
        int off = r*40 + c;
        float qv[8], kvv[8]; float qs = 0.f, ks2 = 0.f;
        #pragma unroll
        for (int i = 0; i < 8; i++) {
            qv[i] = sm[i*PS + off]; qs += qv[i]*qv[i];
            kvv[i] = sm[(8+i)*PS + off]; ks2 += kvv[i]*kvv[i];
        }
        float qsc = 1.f/(sqrtf(qs) + 1e-6f);
        float ksc = 1.f/(sqrtf(ks2) + 1e-6f);
        #pragma unroll
        for (int i = 0; i < 8; i++) {
            sm[i*PS + off] = qv[i]*qsc;
            sm[(8+i)*PS + off] = kvv[i]*ksc;
        }
    }
    __syncthreads();
    float acc[4] = {0.f,0.f,0.f,0.f};
    for (int ci = 0; ci < 16; ci++) {
        const float* pl = sm + ci*PS;
        #pragma unroll
        for (int ky = 0; ky < WS; ky++) {
            const float4* rp = (const float4*)&pl[(row+ky)*40 + cg*4];
            float f[12];
            *(float4*)&f[0] = rp[0]; *(float4*)&f[4] = rp[1];
            if (WS + 3 > 8) *(float4*)&f[8] = rp[2];
            #pragma unroll
            for (int kx = 0; kx < WS; kx++) {
                float wv = wsm[ci*WS*WS + ky*WS + kx];
                #pragma unroll
                for (int cx = 0; cx < 4; cx++) acc[cx] += wv*f[cx+kx];
            }
        }
    }
    float bb2 = __ldg(&bias[hw]);
    size_t o = ((size_t)(b*HEADS + hh))*NN + (size_t)(gy0+row)*WW + gx0 + cg*4;
    float4 r4;
    r4.x = 1.f/(1.f + expf(-(acc[0]+bb2)));
    r4.y = 1.f/(1.f + expf(-(acc[1]+bb2)));
    r4.z = 1.f/(1.f + expf(-(acc[2]+bb2)));
    r4.w = 1.f/(1.f + expf(-(acc[3]+bb2)));
    *(float4*)&refine[o] = r4;
}

// ---------------- combine (fused q-norm) ----------------
__global__ void combine_kernel(const float* __restrict__ qkv, const float* __restrict__ attnm,
                               const float* __restrict__ refine, const float* __restrict__ g1,
                               const float* __restrict__ xsca, const float* __restrict__ temp,
                               float* __restrict__ comb)
{
    int z = blockIdx.y; int b = z >> 3; int hh = z & 7;
    __shared__ float am[80];
    if (threadIdx.x < 80) am[threadIdx.x] = attnm[z*80 + threadIdx.x];
    __syncthreads();
    int n = blockIdx.x * 256 + threadIdx.x;
    float q[8]; float qs = 0.f;
    size_t qb = ((size_t)b*C3 + hh*CHD)*NN + n;
    #pragma unroll
    for (int i = 0; i < 8; i++) { q[i] = qkv[qb + i*NN]; qs += q[i]*q[i]; }
    float qsc = 1.f/(sqrtf(qs) + 1e-6f);
    #pragma unroll
    for (int i = 0; i < 8; i++) q[i] *= qsc;
    float den = (float)NN + 1e-6f;
    #pragma unroll
    for (int i = 0; i < 8; i++) den += q[i]*am[64 + i];
    float scale = __ldg(&temp[hh]) * refine[(size_t)z*NN + n] / den;
    #pragma unroll
    for (int j = 0; j < 8; j++) {
        float num = am[72 + j];
        #pragma unroll
        for (int i = 0; i < 8; i++) num += q[i]*am[i*8 + j];
        int c = hh*CHD + j;
        size_t o = ((size_t)b*CC + c)*NN + n;
        comb[o] = num * scale * __ldg(&xsca[b*CC + c]) * g1[o];
    }
}

// ---------------- launch ----------------
extern "C" void kernel_launch(void* const* d_in, const int* in_sizes, int n_in,
                              void* d_out, int out_size)
{
    const float* x      = (const float*)d_in[0];
    const float* ln1_w  = (const float*)d_in[1];
    const float* sca_w  = (const float*)d_in[2];
    const float* sca_b  = (const float*)d_in[3];
    const float* dw1_w  = (const float*)d_in[4];
    const float* dw2_w  = (const float*)d_in[5];
    const float* qkv_w  = (const float*)d_in[6];
    const float* qkv_dw = (const float*)d_in[7];
    const float* temp   = (const float*)d_in[8];
    const float* r3_w   = (const float*)d_in[9];
    const float* r3_b   = (const float*)d_in[10];
    const float* r5_w   = (const float*)d_in[11];
    const float* r5_b   = (const float*)d_in[12];
    const float* r7_w   = (const float*)d_in[13];
    const float* r7_b   = (const float*)d_in[14];
    const float* proj_w = (const float*)d_in[15];
    const float* ln2_w  = (const float*)d_in[16];
    const float* pin_w  = (const float*)d_in[17];
    const float* ffn_dw = (const float*)d_in[18];
    const float* pout_w = (const float*)d_in[19];
    float* out = (float*)d_out;

    float *py, *pxT, *pxi1, *pg1, *pbig, *pqkv, *pu, *pg2, *pref, *pmp, *pxsca, *ppart, *pattnm;
    cudaGetSymbolAddress((void**)&py,    d_y);
    cudaGetSymbolAddress((void**)&pxT,   d_xT);
    cudaGetSymbolAddress((void**)&pxi1,  d_xi1);
    cudaGetSymbolAddress((void**)&pg1,   d_g1);
    cudaGetSymbolAddress((void**)&pbig,  d_big);
    cudaGetSymbolAddress((void**)&pqkv,  d_qkv);
    cudaGetSymbolAddress((void**)&pu,    d_u);
    cudaGetSymbolAddress((void**)&pg2,   d_g2);
    cudaGetSymbolAddress((void**)&pref,  d_ref);
    cudaGetSymbolAddress((void**)&pmp,   d_meanpart);
    cudaGetSymbolAddress((void**)&pxsca, d_xsca);
    cudaGetSymbolAddress((void**)&ppart, d_attnpart);
    cudaGetSymbolAddress((void**)&pattnm,d_attnm);

    // dynamic-smem capacity for refine templates (idempotent)
    static_assert(true, "");
    cudaFuncSetAttribute(refine_kernel<3>, cudaFuncAttributeMaxDynamicSharedMemorySize, 16*(34*40)*4 + 16*9*4);
    cudaFuncSetAttribute(refine_kernel<5>, cudaFuncAttributeMaxDynamicSharedMemorySize, 16*(36*40)*4 + 16*25*4);
    cudaFuncSetAttribute(refine_kernel<7>, cudaFuncAttributeMaxDynamicSharedMemorySize, 16*(38*40)*4 + 16*49*4);

    // LN1 (+ transpose of input for residual)
    ln_kernel<0><<<BN/256, 256>>>(x, ln1_w, py, pxT);
    mean1_kernel<<<dim3(64, BB*CC), 256>>>(py, pmp);
    xsca_kernel<<<BB, CC>>>(pmp, sca_w, sca_b, pxsca);
    // 1x1 convs: qkv (192ch) and dw1 (128ch)
    conv1x1_kernel<CC, C3, 0><<<dim3(NN/128, 3, BB), 256>>>(py, qkv_w, pbig, nullptr);
    conv1x1_kernel<CC, C2, 0><<<dim3(NN/128, 2, BB), 256>>>(py, dw1_w, pu, nullptr);
    // depthwise 3x3 on qkv (raw output; norms fused downstream)
    dw3_kernel<C3><<<dim3(8, 8, BB*C3), 256>>>(pbig, qkv_dw, pqkv);
    // grouped conv dw2 + gelu -> g1
    dw2gelu_kernel<<<dim3(8, 8, BB*CC), 256>>>(pu, dw2_w, pg1);
    // global reductions k@v, ksum, vsum (k-norm fused)
    attnred1_kernel<<<dim3(64, 32), 256>>>(pqkv, ppart);
    attnred2_kernel<<<32, 128>>>(ppart, pattnm);
    // refine conv + sigmoid (q/k-norm fused), one launch per window size
    refine_kernel<3><<<dim3(8, 8, BB*2), 256, 16*(34*40)*4 + 16*9*4>>>(pqkv, r3_w, r3_b, 0, 2, pref);
    refine_kernel<5><<<dim3(8, 8, BB*3), 256, 16*(36*40)*4 + 16*25*4>>>(pqkv, r5_w, r5_b, 2, 3, pref);
    refine_kernel<7><<<dim3(8, 8, BB*3), 256, 16*(38*40)*4 + 16*49*4>>>(pqkv, r7_w, r7_b, 5, 3, pref);
    // combine -> comb (reuse d_y)
    combine_kernel<<<dim3(NN/256, BB*HEADS), 256>>>(pqkv, pattnm, pref, pg1, pxsca, temp, py);
    // proj 1x1 + residual
    conv1x1_kernel<CC, CC, 1><<<dim3(NN/128, 1, BB), 256>>>(py, proj_w, pxi1, pxT);
    // LN2
    ln_kernel<1><<<BN/256, 256>>>(pxi1, ln2_w, py, nullptr);
    // FFN: pin 64->340
    conv1x1_kernel<CC, HID2, 0><<<dim3(NN/128, 6, BB), 256>>>(py, pin_w, pbig, nullptr);
    // FFN depthwise + gated gelu
    ffndw_kernel<<<dim3(8, 8, BB*HIDD), 256>>>(pbig, ffn_dw, pg2);
    // pout 170->64 + residual -> output
    conv1x1_kernel<HIDD, CC, 1><<<dim3(NN/128, 1, BB), 256>>>(pg2, pout_w, out, pxi1);
}